// round 7
// baseline (speedup 1.0000x reference)
#include <cuda_runtime.h>

typedef unsigned long long ull;

#define X7    (7*1048576)      // x[7] offset (floats)
#define W7OFF (7*8*4096)       // weights[7] offset (floats)

// Scratch (device globals — no allocations allowed)
__device__ float g_uhl[8*16384*64];  // [j][b][e] 32MB
__device__ float g_n2[8*16384];      // [j][b]
__device__ float g_umpart[16*512];   // per-block partial sums of u over b
__device__ float g_uhm[4096];        // [i][j][e]
__device__ float g_B[64];
__device__ float g_t[512];           // [j][d]
__device__ float g_c[8];             // final-iteration c_j

__device__ __forceinline__ void fma2(ull &acc, ull a, ull b) {
    asm("fma.rn.f32x2 %0, %1, %2, %0;" : "+l"(acc) : "l"(a), "l"(b));
}
__device__ __forceinline__ ull pack2(float x) {
    unsigned u = __float_as_uint(x);
    ull r; asm("mov.b64 %0, {%1, %1};" : "=l"(r) : "r"(u)); return r;
}
__device__ __forceinline__ float2 unpack2(ull v) {
    unsigned lo, hi;
    asm("mov.b64 {%0, %1}, %2;" : "=r"(lo), "=r"(hi) : "l"(v));
    return make_float2(__uint_as_float(lo), __uint_as_float(hi));
}
__device__ __forceinline__ float squash_scal(float cj, float n2v) {
    float s2 = cj*cj*n2v;
    return cj*s2 / ((1.f+s2)*sqrtf(s2+1e-9f));
}
// x[7] memory row for u-row b:  u[b,7,d] = x[7, b&31, b>>5, d]
__device__ __forceinline__ int xrow(int b) {
    return (b & 31)*512 + (b >> 5);
}

// sum over rows of x[i] -> g_umpart[bx][i*64+d]. float4 loads, no atomics.
__global__ __launch_bounds__(256) void k_umean(const float* __restrict__ x) {
    __shared__ float4 red[16][16];
    int i = blockIdx.y, bx = blockIdx.x, t = threadIdx.x;
    int dq = (t & 15) * 4, g = t >> 4;          // 16 d-quads, 16 row-groups
    const float* xp = x + i*1048576 + (bx*1024 + g*64)*64 + dq;
    float4 acc = make_float4(0.f,0.f,0.f,0.f);
    #pragma unroll 8
    for (int m = 0; m < 64; m++) {
        float4 v = *(const float4*)(xp + m*64);
        acc.x += v.x; acc.y += v.y; acc.z += v.z; acc.w += v.w;
    }
    red[g][t & 15] = acc;
    __syncthreads();
    if (t < 16) {
        float4 s = make_float4(0.f,0.f,0.f,0.f);
        #pragma unroll
        for (int gg = 0; gg < 16; gg++) {
            float4 v = red[gg][t];
            s.x += v.x; s.y += v.y; s.z += v.z; s.w += v.w;
        }
        *(float4*)&g_umpart[bx*512 + i*64 + t*4] = s;
    }
}

// uhm[i,j,e] = sum_d W[i,j,d,e] * umean[i,d]   (16 blocks x 4 ij each)
__global__ __launch_bounds__(256) void k_uhm(const float* __restrict__ w) {
    __shared__ float um[512];
    int t = threadIdx.x;           // 256
    #pragma unroll
    for (int o = 0; o < 2; o++) {
        int idx = t + 256*o;
        float s = 0.f;
        #pragma unroll
        for (int bx = 0; bx < 16; bx++) s += g_umpart[bx*512 + idx];
        um[idx] = s * (1.f/16384.f);
    }
    __syncthreads();
    int ij = blockIdx.x*4 + (t >> 6), e = t & 63;
    int i = ij >> 3;
    const float* wp = w + ij*4096 + e;
    const float* up = um + i*64;
    float s = 0.f;
    #pragma unroll 8
    for (int d = 0; d < 64; d++) s += wp[d*64] * up[d];
    g_uhm[ij*64 + e] = s;
}

// uhl[j,b,e] = sum_d u[b,7,d]*W7[j,d,e]; n2[j,b] = sum_e uhl^2
// grid (256 p-blocks, 8 j); 64 rows/block, one j per block, one sync.
__global__ __launch_bounds__(128, 8) void k_gemm(const float* __restrict__ x,
                                                 const float* __restrict__ w) {
    __shared__ float xs[64*64];    // [d][row] 16KB
    __shared__ float ws[64*64];    // [d][col] 16KB
    int t = threadIdx.x;           // 128
    int p0 = blockIdx.x * 64;      // b-block base
    int j = blockIdx.y;

    if (blockIdx.x == 0 && j == 0) {   // zero routing state for this replay
        g_t[t] = 0.f; g_t[t+128] = 0.f; g_t[t+256] = 0.f; g_t[t+384] = 0.f;
        if (t < 64) g_B[t] = 0.f;
    }

    {   // load + transpose 64 u-rows (gather from permuted x layout)
        int rp_ = t & 31, q = t >> 5;      // q: d-chunk of 16
        int bA = p0 + 2*rp_;
        const float* pa = x + X7 + xrow(bA)*64 + q*16;
        const float* pb = x + X7 + xrow(bA+1)*64 + q*16;
        #pragma unroll
        for (int i = 0; i < 4; i++) {
            float4 a = *(const float4*)(pa + 4*i);
            float4 b = *(const float4*)(pb + 4*i);
            int d0 = q*16 + 4*i;
            xs[(d0+0)*64 + 2*rp_] = a.x; xs[(d0+0)*64 + 2*rp_+1] = b.x;
            xs[(d0+1)*64 + 2*rp_] = a.y; xs[(d0+1)*64 + 2*rp_+1] = b.y;
            xs[(d0+2)*64 + 2*rp_] = a.z; xs[(d0+2)*64 + 2*rp_+1] = b.z;
            xs[(d0+3)*64 + 2*rp_] = a.w; xs[(d0+3)*64 + 2*rp_+1] = b.w;
        }
    }
    {   // fill W tile (natural layout)
        const float* W7p = w + W7OFF + j*4096;
        #pragma unroll
        for (int k = 0; k < 8; k++) {
            int idx = t + 128*k;
            *(float4*)(ws + idx*4) = *(const float4*)(W7p + idx*4);
        }
    }
    __syncthreads();

    int cg = t & 7, rq = t >> 3;
    int r0 = rq * 4;

    // acc[r][m]: m=0,1 -> cols 4cg..4cg+3 ; m=2,3 -> cols 32+4cg..+3
    ull acc[4][4];
    #pragma unroll
    for (int r = 0; r < 4; r++)
        #pragma unroll
        for (int m = 0; m < 4; m++) acc[r][m] = 0ULL;

    #pragma unroll 8
    for (int d = 0; d < 64; d++) {
        ulonglong2 w0 = *(const ulonglong2*)&ws[d*64 + cg*4];
        ulonglong2 w1 = *(const ulonglong2*)&ws[d*64 + 32 + cg*4];
        ull xr[4];
        #pragma unroll
        for (int r = 0; r < 4; r++) xr[r] = pack2(xs[d*64 + r0 + r]);
        #pragma unroll
        for (int r = 0; r < 4; r++) {
            fma2(acc[r][0], xr[r], w0.x);
            fma2(acc[r][1], xr[r], w0.y);
            fma2(acc[r][2], xr[r], w1.x);
            fma2(acc[r][3], xr[r], w1.y);
        }
    }

    #pragma unroll
    for (int r = 0; r < 4; r++) {
        float2 v0 = unpack2(acc[r][0]), v1 = unpack2(acc[r][1]);
        float2 v2 = unpack2(acc[r][2]), v3 = unpack2(acc[r][3]);
        int row = p0 + r0 + r;
        float* base = g_uhl + j*1048576 + row*64;
        *(float4*)(base + 4*cg)      = make_float4(v0.x, v0.y, v1.x, v1.y);
        *(float4*)(base + 32 + 4*cg) = make_float4(v2.x, v2.y, v3.x, v3.y);

        float s = v0.x*v0.x + v0.y*v0.y + v1.x*v1.x + v1.y*v1.y
                + v2.x*v2.x + v2.y*v2.y + v3.x*v3.x + v3.y*v3.y;
        #pragma unroll
        for (int off = 1; off < 8; off <<= 1)
            s += __shfl_xor_sync(~0u, s, off);
        if (cg == 0) g_n2[j*16384 + row] = s;
    }
}

// one routing reduction: c=softmax(B)[7,:]; t[j,d] += scal(b,j)*u[b,7,d]
__global__ __launch_bounds__(256) void k_route1(const float* __restrict__ x) {
    __shared__ float c_s[8];
    __shared__ float scal_s[256*8];
    __shared__ float red[4][512];
    int t = threadIdx.x;
    if (t < 8) {
        float m = g_B[t];
        #pragma unroll
        for (int i = 1; i < 8; i++) m = fmaxf(m, g_B[i*8+t]);
        float sum = 0.f, e7 = 0.f;
        #pragma unroll
        for (int i = 0; i < 8; i++) {
            float e = expf(g_B[i*8+t] - m);
            sum += e; if (i == 7) e7 = e;
        }
        c_s[t] = e7/sum;
    }
    __syncthreads();
    int p0 = blockIdx.x * 256;
    {
        int b = p0 + t;
        #pragma unroll
        for (int j = 0; j < 8; j++)
            scal_s[t*8+j] = squash_scal(c_s[j], g_n2[j*16384 + b]);
    }
    __syncthreads();
    int d = t & 63, g = t >> 6;
    float acc[8] = {0,0,0,0,0,0,0,0};
    #pragma unroll 8
    for (int m = 0; m < 64; m++) {
        int r = g*64 + m;
        int b = p0 + r;
        float xv = x[X7 + xrow(b)*64 + d];
        #pragma unroll
        for (int j = 0; j < 8; j++) acc[j] += scal_s[r*8+j] * xv;
    }
    #pragma unroll
    for (int j = 0; j < 8; j++) red[g][j*64+d] = acc[j];
    __syncthreads();
    #pragma unroll
    for (int o = 0; o < 2; o++) {
        int idx = t + 256*o;
        atomicAdd(&g_t[idx], red[0][idx]+red[1][idx]+red[2][idx]+red[3][idx]);
    }
}

// vmean[j,e] = (1/16384)*sum_d W7[j,d,e]*t[j,d]; B += uhm.vmean; g_c=softmax(B)[7]
__global__ void k_route2(const float* __restrict__ w) {
    __shared__ float ts[512], vm[512];
    int t = threadIdx.x;           // 256
    ts[t] = g_t[t]; ts[t+256] = g_t[t+256];
    __syncthreads();
    g_t[t] = 0.f; g_t[t+256] = 0.f;
    const float* W7p = w + W7OFF;
    #pragma unroll
    for (int o = 0; o < 2; o++) {
        int idx = t + 256*o, j = idx >> 6, e = idx & 63;
        const float* wp = W7p + j*4096 + e;
        const float* tp = ts + j*64;
        float s = 0.f;
        #pragma unroll 8
        for (int d = 0; d < 64; d++) s += wp[d*64] * tp[d];
        vm[idx] = s * (1.f/16384.f);
    }
    __syncthreads();
    if (t < 64) {
        int j = t & 7;
        float s = 0.f;
        #pragma unroll 8
        for (int e = 0; e < 64; e++) s += g_uhm[t*64 + e] * vm[j*64 + e];
        g_B[t] += s;
    }
    __syncthreads();
    if (t < 8) {
        float m = g_B[t];
        #pragma unroll
        for (int i = 1; i < 8; i++) m = fmaxf(m, g_B[i*8+t]);
        float sum = 0.f, e7 = 0.f;
        #pragma unroll
        for (int i = 0; i < 8; i++) {
            float e = expf(g_B[i*8+t] - m);
            sum += e; if (i == 7) e7 = e;
        }
        g_c[t] = e7/sum;
    }
}

// out[j,b,e] = scal3(j,b) * uhl[j,b,e]  (pure stream; output position == b)
__global__ void k_out(float* __restrict__ out) {
    __shared__ float scal_s[128];
    int j = blockIdx.y, p0 = blockIdx.x * 128, t = threadIdx.x;
    if (t < 128) scal_s[t] = squash_scal(g_c[j], g_n2[j*16384 + p0 + t]);
    __syncthreads();
    const float4* src = (const float4*)(g_uhl + j*1048576 + p0*64);
    float4* dst = (float4*)(out + j*1048576 + p0*64);
    #pragma unroll
    for (int k = 0; k < 8; k++) {
        int idx = k*256 + t;       // 2048 float4
        float4 v = src[idx];
        float s = scal_s[idx >> 4];
        v.x *= s; v.y *= s; v.z *= s; v.w *= s;
        dst[idx] = v;
    }
}

extern "C" void kernel_launch(void* const* d_in, const int* in_sizes, int n_in,
                              void* d_out, int out_size) {
    const float* x = (const float*)d_in[0];
    const float* w = (const float*)d_in[1];
    float* out = (float*)d_out;
    k_gemm<<<dim3(256, 8), 128>>>(x, w);
    k_umean<<<dim3(16, 8), 256>>>(x);
    k_uhm<<<16, 256>>>(w);
    k_route1<<<64, 256>>>(x);
    k_route2<<<1, 256>>>(w);
    k_route1<<<64, 256>>>(x);
    k_route2<<<1, 256>>>(w);
    k_out<<<dim3(128, 8), 256>>>(out);
}

// round 8
// speedup vs baseline: 1.1350x; 1.1350x over previous
#include <cuda_runtime.h>

typedef unsigned long long ull;

#define X7    (7*1048576)      // x[7] offset (floats)
#define W7OFF (7*8*4096)       // weights[7] offset (floats)

// Scratch (device globals — no allocations allowed)
__device__ float g_uhl[8*16384*64];  // [j][b][e] 32MB
__device__ float g_n2[8*16384];      // [j][b]
__device__ float g_umpart[16*512];   // per-block partial sums of u over b
__device__ float g_uhm[4096];        // [i][j][e]
__device__ float g_B[64];
__device__ float g_t[512];           // [j][d]
__device__ float g_c[8];             // final-iteration c_j

__device__ __forceinline__ void fma2(ull &acc, ull a, ull b) {
    asm("fma.rn.f32x2 %0, %1, %2, %0;" : "+l"(acc) : "l"(a), "l"(b));
}
__device__ __forceinline__ ull pack2(float x) {
    unsigned u = __float_as_uint(x);
    ull r; asm("mov.b64 %0, {%1, %1};" : "=l"(r) : "r"(u)); return r;
}
__device__ __forceinline__ float2 unpack2(ull v) {
    unsigned lo, hi;
    asm("mov.b64 {%0, %1}, %2;" : "=r"(lo), "=r"(hi) : "l"(v));
    return make_float2(__uint_as_float(lo), __uint_as_float(hi));
}
__device__ __forceinline__ float squash_scal(float cj, float n2v) {
    float s2 = cj*cj*n2v;
    return cj*s2 / ((1.f+s2)*sqrtf(s2+1e-9f));
}
// x[7] memory row for u-row b:  u[b,7,d] = x[7, b&31, b>>5, d]
__device__ __forceinline__ int xrow(int b) {
    return (b & 31)*512 + (b >> 5);
}

// sum over rows of x[i] -> g_umpart[bx][i*64+d]. float4 loads, no atomics.
__global__ __launch_bounds__(256) void k_umean(const float* __restrict__ x) {
    __shared__ float4 red[16][16];
    int i = blockIdx.y, bx = blockIdx.x, t = threadIdx.x;
    int dq = (t & 15) * 4, g = t >> 4;          // 16 d-quads, 16 row-groups
    const float* xp = x + i*1048576 + (bx*1024 + g*64)*64 + dq;
    float4 acc = make_float4(0.f,0.f,0.f,0.f);
    #pragma unroll 8
    for (int m = 0; m < 64; m++) {
        float4 v = *(const float4*)(xp + m*64);
        acc.x += v.x; acc.y += v.y; acc.z += v.z; acc.w += v.w;
    }
    red[g][t & 15] = acc;
    __syncthreads();
    if (t < 16) {
        float4 s = make_float4(0.f,0.f,0.f,0.f);
        #pragma unroll
        for (int gg = 0; gg < 16; gg++) {
            float4 v = red[gg][t];
            s.x += v.x; s.y += v.y; s.z += v.z; s.w += v.w;
        }
        *(float4*)&g_umpart[bx*512 + i*64 + t*4] = s;
    }
}

// uhm[i,j,e] = sum_d W[i,j,d,e] * umean[i,d]   (16 blocks x 4 ij each)
__global__ __launch_bounds__(256) void k_uhm(const float* __restrict__ w) {
    __shared__ float um[512];
    int t = threadIdx.x;           // 256
    #pragma unroll
    for (int o = 0; o < 2; o++) {
        int idx = t + 256*o;
        float s = 0.f;
        #pragma unroll
        for (int bx = 0; bx < 16; bx++) s += g_umpart[bx*512 + idx];
        um[idx] = s * (1.f/16384.f);
    }
    __syncthreads();
    int ij = blockIdx.x*4 + (t >> 6), e = t & 63;
    int i = ij >> 3;
    const float* wp = w + ij*4096 + e;
    const float* up = um + i*64;
    float s = 0.f;
    #pragma unroll 8
    for (int d = 0; d < 64; d++) s += wp[d*64] * up[d];
    g_uhm[ij*64 + e] = s;
}

// uhl[j,b,e] = sum_d u[b,7,d]*W7[j,d,e]; n2[j,b] = sum_e uhl^2
// grid (256 p-blocks, 4 j-pairs); 64 rows/block, 2 j per block.
__global__ __launch_bounds__(128) void k_gemm(const float* __restrict__ x,
                                              const float* __restrict__ w) {
    __shared__ float xs[64*64];    // [d][row] 16KB
    __shared__ float ws[64*64];    // [d][col] 16KB
    int t = threadIdx.x;           // 128
    int p0 = blockIdx.x * 64;      // b-block base
    int j0 = blockIdx.y * 2;

    if (blockIdx.x == 0 && blockIdx.y == 0) {   // zero routing state per replay
        g_t[t] = 0.f; g_t[t+128] = 0.f; g_t[t+256] = 0.f; g_t[t+384] = 0.f;
        if (t < 64) g_B[t] = 0.f;
    }

    {   // load + transpose 64 u-rows (gather from permuted x layout)
        int rp_ = t & 31, q = t >> 5;      // q: d-chunk of 16
        int bA = p0 + 2*rp_;
        const float* pa = x + X7 + xrow(bA)*64 + q*16;
        const float* pb = x + X7 + xrow(bA+1)*64 + q*16;
        #pragma unroll
        for (int i = 0; i < 4; i++) {
            float4 a = *(const float4*)(pa + 4*i);
            float4 b = *(const float4*)(pb + 4*i);
            int d0 = q*16 + 4*i;
            xs[(d0+0)*64 + 2*rp_] = a.x; xs[(d0+0)*64 + 2*rp_+1] = b.x;
            xs[(d0+1)*64 + 2*rp_] = a.y; xs[(d0+1)*64 + 2*rp_+1] = b.y;
            xs[(d0+2)*64 + 2*rp_] = a.z; xs[(d0+2)*64 + 2*rp_+1] = b.z;
            xs[(d0+3)*64 + 2*rp_] = a.w; xs[(d0+3)*64 + 2*rp_+1] = b.w;
        }
    }

    int cg = t & 7, rq = t >> 3;
    int r0 = rq * 4;

    #pragma unroll
    for (int jj = 0; jj < 2; jj++) {
        int j = j0 + jj;
        __syncthreads();
        {   // fill W tile (natural layout)
            const float* W7p = w + W7OFF + j*4096;
            #pragma unroll
            for (int k = 0; k < 8; k++) {
                int idx = t + 128*k;
                *(float4*)(ws + idx*4) = *(const float4*)(W7p + idx*4);
            }
        }
        __syncthreads();

        // acc[r][m]: m=0,1 -> cols 4cg..4cg+3 ; m=2,3 -> cols 32+4cg..+3
        ull acc[4][4];
        #pragma unroll
        for (int r = 0; r < 4; r++)
            #pragma unroll
            for (int m = 0; m < 4; m++) acc[r][m] = 0ULL;

        #pragma unroll 8
        for (int d = 0; d < 64; d++) {
            ulonglong2 w0 = *(const ulonglong2*)&ws[d*64 + cg*4];
            ulonglong2 w1 = *(const ulonglong2*)&ws[d*64 + 32 + cg*4];
            ull xr[4];
            #pragma unroll
            for (int r = 0; r < 4; r++) xr[r] = pack2(xs[d*64 + r0 + r]);
            #pragma unroll
            for (int r = 0; r < 4; r++) {
                fma2(acc[r][0], xr[r], w0.x);
                fma2(acc[r][1], xr[r], w0.y);
                fma2(acc[r][2], xr[r], w1.x);
                fma2(acc[r][3], xr[r], w1.y);
            }
        }

        #pragma unroll
        for (int r = 0; r < 4; r++) {
            float2 v0 = unpack2(acc[r][0]), v1 = unpack2(acc[r][1]);
            float2 v2 = unpack2(acc[r][2]), v3 = unpack2(acc[r][3]);
            int row = p0 + r0 + r;
            float* base = g_uhl + j*1048576 + row*64;
            *(float4*)(base + 4*cg)      = make_float4(v0.x, v0.y, v1.x, v1.y);
            *(float4*)(base + 32 + 4*cg) = make_float4(v2.x, v2.y, v3.x, v3.y);

            float s = v0.x*v0.x + v0.y*v0.y + v1.x*v1.x + v1.y*v1.y
                    + v2.x*v2.x + v2.y*v2.y + v3.x*v3.x + v3.y*v3.y;
            #pragma unroll
            for (int off = 1; off < 8; off <<= 1)
                s += __shfl_xor_sync(~0u, s, off);
            if (cg == 0) g_n2[j*16384 + row] = s;
        }
    }
}

// one routing reduction: c=softmax(B)[7,:]; t[j,d] += scal(b,j)*u[b,7,d]
// grid 128 blocks x 128 rows; deep-MLP main loop (unroll 8).
__global__ __launch_bounds__(256) void k_route1(const float* __restrict__ x) {
    __shared__ float c_s[8];
    __shared__ float scal_s[128*8];
    __shared__ float red[4][512];
    int t = threadIdx.x;
    if (t < 8) {
        float m = g_B[t];
        #pragma unroll
        for (int i = 1; i < 8; i++) m = fmaxf(m, g_B[i*8+t]);
        float sum = 0.f, e7 = 0.f;
        #pragma unroll
        for (int i = 0; i < 8; i++) {
            float e = expf(g_B[i*8+t] - m);
            sum += e; if (i == 7) e7 = e;
        }
        c_s[t] = e7/sum;
    }
    __syncthreads();
    int p0 = blockIdx.x * 128;
    {   // scal table: thread t -> row t>>1, 4 j's
        int r = t >> 1, jh = (t & 1) * 4;
        int b = p0 + r;
        #pragma unroll
        for (int k = 0; k < 4; k++)
            scal_s[r*8 + jh + k] = squash_scal(c_s[jh+k], g_n2[(jh+k)*16384 + b]);
    }
    __syncthreads();
    int d = t & 63, g = t >> 6;          // 4 groups x 32 rows
    float acc[8] = {0,0,0,0,0,0,0,0};
    const float* xb = x + X7 + d;
    #pragma unroll 8
    for (int m = 0; m < 32; m++) {
        int r = g*32 + m;
        float xv = xb[xrow(p0 + r)*64];
        #pragma unroll
        for (int j = 0; j < 8; j++) acc[j] += scal_s[r*8+j] * xv;
    }
    #pragma unroll
    for (int j = 0; j < 8; j++) red[g][j*64+d] = acc[j];
    __syncthreads();
    #pragma unroll
    for (int o = 0; o < 2; o++) {
        int idx = t + 256*o;
        atomicAdd(&g_t[idx], red[0][idx]+red[1][idx]+red[2][idx]+red[3][idx]);
    }
}

// vmean[j,e] = (1/16384)*sum_d W7[j,d,e]*t[j,d]; B += uhm.vmean; g_c=softmax(B)[7]
__global__ void k_route2(const float* __restrict__ w) {
    __shared__ float ts[512], vm[512];
    int t = threadIdx.x;           // 256
    ts[t] = g_t[t]; ts[t+256] = g_t[t+256];
    __syncthreads();
    g_t[t] = 0.f; g_t[t+256] = 0.f;
    const float* W7p = w + W7OFF;
    #pragma unroll
    for (int o = 0; o < 2; o++) {
        int idx = t + 256*o, j = idx >> 6, e = idx & 63;
        const float* wp = W7p + j*4096 + e;
        const float* tp = ts + j*64;
        float s = 0.f;
        #pragma unroll 8
        for (int d = 0; d < 64; d++) s += wp[d*64] * tp[d];
        vm[idx] = s * (1.f/16384.f);
    }
    __syncthreads();
    if (t < 64) {
        int j = t & 7;
        float s = 0.f;
        #pragma unroll 8
        for (int e = 0; e < 64; e++) s += g_uhm[t*64 + e] * vm[j*64 + e];
        g_B[t] += s;
    }
    __syncthreads();
    if (t < 8) {
        float m = g_B[t];
        #pragma unroll
        for (int i = 1; i < 8; i++) m = fmaxf(m, g_B[i*8+t]);
        float sum = 0.f, e7 = 0.f;
        #pragma unroll
        for (int i = 0; i < 8; i++) {
            float e = expf(g_B[i*8+t] - m);
            sum += e; if (i == 7) e7 = e;
        }
        g_c[t] = e7/sum;
    }
}

// out[j,b,e] = scal3(j,b) * uhl[j,b,e]  (pure stream; output position == b)
__global__ void k_out(float* __restrict__ out) {
    __shared__ float scal_s[128];
    int j = blockIdx.y, p0 = blockIdx.x * 128, t = threadIdx.x;
    if (t < 128) scal_s[t] = squash_scal(g_c[j], g_n2[j*16384 + p0 + t]);
    __syncthreads();
    const float4* src = (const float4*)(g_uhl + j*1048576 + p0*64);
    float4* dst = (float4*)(out + j*1048576 + p0*64);
    #pragma unroll
    for (int k = 0; k < 8; k++) {
        int idx = k*256 + t;       // 2048 float4
        float4 v = src[idx];
        float s = scal_s[idx >> 4];
        v.x *= s; v.y *= s; v.z *= s; v.w *= s;
        dst[idx] = v;
    }
}

extern "C" void kernel_launch(void* const* d_in, const int* in_sizes, int n_in,
                              void* d_out, int out_size) {
    const float* x = (const float*)d_in[0];
    const float* w = (const float*)d_in[1];
    float* out = (float*)d_out;
    k_gemm<<<dim3(256, 4), 128>>>(x, w);
    k_umean<<<dim3(16, 8), 256>>>(x);
    k_uhm<<<16, 256>>>(w);
    k_route1<<<128, 256>>>(x);
    k_route2<<<1, 256>>>(w);
    k_route1<<<128, 256>>>(x);
    k_route2<<<1, 256>>>(w);
    k_out<<<dim3(128, 8), 256>>>(out);
}

// round 9
// speedup vs baseline: 1.1903x; 1.0487x over previous
#include <cuda_runtime.h>

typedef unsigned long long ull;

#define X7    (7*1048576)      // x[7] offset (floats)
#define W7OFF (7*8*4096)       // weights[7] offset (floats)

// Scratch (device globals — no allocations allowed)
__device__ float g_uhl[8*16384*64];  // [j][b][e] 32MB
__device__ float g_n2[8*16384];      // [j][b]
__device__ float g_umpart[16*512];   // per-block partial sums of u over b
__device__ float g_uhm[4096];        // [i][j][e]
__device__ float g_B[64];
__device__ float g_t[512];           // [j][d]
__device__ float g_c[8];             // final-iteration c_j

__device__ __forceinline__ void fma2(ull &acc, ull a, ull b) {
    asm("fma.rn.f32x2 %0, %1, %2, %0;" : "+l"(acc) : "l"(a), "l"(b));
}
__device__ __forceinline__ ull pack2(float x) {
    unsigned u = __float_as_uint(x);
    ull r; asm("mov.b64 %0, {%1, %1};" : "=l"(r) : "r"(u)); return r;
}
__device__ __forceinline__ float2 unpack2(ull v) {
    unsigned lo, hi;
    asm("mov.b64 {%0, %1}, %2;" : "=r"(lo), "=r"(hi) : "l"(v));
    return make_float2(__uint_as_float(lo), __uint_as_float(hi));
}
__device__ __forceinline__ float squash_scal(float cj, float n2v) {
    float s2 = cj*cj*n2v;
    return cj*s2 / ((1.f+s2)*sqrtf(s2+1e-9f));
}
// x[7] memory row for u-row b:  u[b,7,d] = x[7, b&31, b>>5, d]
__device__ __forceinline__ int xrow(int b) {
    return (b & 31)*512 + (b >> 5);
}

// sum over rows of x[i] -> g_umpart[bx][i*64+d]. float4 loads, no atomics.
__global__ __launch_bounds__(256) void k_umean(const float* __restrict__ x) {
    __shared__ float4 red[16][16];
    int i = blockIdx.y, bx = blockIdx.x, t = threadIdx.x;
    int dq = (t & 15) * 4, g = t >> 4;          // 16 d-quads, 16 row-groups
    const float* xp = x + i*1048576 + (bx*1024 + g*64)*64 + dq;
    float4 acc = make_float4(0.f,0.f,0.f,0.f);
    #pragma unroll 8
    for (int m = 0; m < 64; m++) {
        float4 v = *(const float4*)(xp + m*64);
        acc.x += v.x; acc.y += v.y; acc.z += v.z; acc.w += v.w;
    }
    red[g][t & 15] = acc;
    __syncthreads();
    if (t < 16) {
        float4 s = make_float4(0.f,0.f,0.f,0.f);
        #pragma unroll
        for (int gg = 0; gg < 16; gg++) {
            float4 v = red[gg][t];
            s.x += v.x; s.y += v.y; s.z += v.z; s.w += v.w;
        }
        *(float4*)&g_umpart[bx*512 + i*64 + t*4] = s;
    }
}

// uhm[i,j,e] = sum_d W[i,j,d,e] * umean[i,d]   (16 blocks x 4 ij each)
__global__ __launch_bounds__(256) void k_uhm(const float* __restrict__ w) {
    __shared__ float um[512];
    int t = threadIdx.x;           // 256
    #pragma unroll
    for (int o = 0; o < 2; o++) {
        int idx = t + 256*o;
        float s = 0.f;
        #pragma unroll
        for (int bx = 0; bx < 16; bx++) s += g_umpart[bx*512 + idx];
        um[idx] = s * (1.f/16384.f);
    }
    __syncthreads();
    int ij = blockIdx.x*4 + (t >> 6), e = t & 63;
    int i = ij >> 3;
    const float* wp = w + ij*4096 + e;
    const float* up = um + i*64;
    float s = 0.f;
    #pragma unroll 8
    for (int d = 0; d < 64; d++) s += wp[d*64] * up[d];
    g_uhm[ij*64 + e] = s;
}

// uhl[j,b,e] = sum_d u[b,7,d]*W7[j,d,e]; n2[j,b] = sum_e uhl^2
// grid (256 p-blocks, 4 j-pairs); 64 rows/block, 2 j per block.
__global__ __launch_bounds__(128) void k_gemm(const float* __restrict__ x,
                                              const float* __restrict__ w) {
    __shared__ float xs[64*64];    // [d][row] 16KB
    __shared__ float ws[64*64];    // [d][col] 16KB
    int t = threadIdx.x;           // 128
    int p0 = blockIdx.x * 64;      // b-block base
    int j0 = blockIdx.y * 2;

    if (blockIdx.x == 0 && blockIdx.y == 0) {   // zero routing state per replay
        g_t[t] = 0.f; g_t[t+128] = 0.f; g_t[t+256] = 0.f; g_t[t+384] = 0.f;
        if (t < 64) g_B[t] = 0.f;
    }

    {   // load + transpose 64 u-rows (gather from permuted x layout)
        int rp_ = t & 31, q = t >> 5;      // q: d-chunk of 16
        int bA = p0 + 2*rp_;
        const float* pa = x + X7 + xrow(bA)*64 + q*16;
        const float* pb = x + X7 + xrow(bA+1)*64 + q*16;
        #pragma unroll
        for (int i = 0; i < 4; i++) {
            float4 a = *(const float4*)(pa + 4*i);
            float4 b = *(const float4*)(pb + 4*i);
            int d0 = q*16 + 4*i;
            xs[(d0+0)*64 + 2*rp_] = a.x; xs[(d0+0)*64 + 2*rp_+1] = b.x;
            xs[(d0+1)*64 + 2*rp_] = a.y; xs[(d0+1)*64 + 2*rp_+1] = b.y;
            xs[(d0+2)*64 + 2*rp_] = a.z; xs[(d0+2)*64 + 2*rp_+1] = b.z;
            xs[(d0+3)*64 + 2*rp_] = a.w; xs[(d0+3)*64 + 2*rp_+1] = b.w;
        }
    }

    int cg = t & 7, rq = t >> 3;
    int r0 = rq * 4;

    #pragma unroll
    for (int jj = 0; jj < 2; jj++) {
        int j = j0 + jj;
        __syncthreads();
        {   // fill W tile (natural layout)
            const float* W7p = w + W7OFF + j*4096;
            #pragma unroll
            for (int k = 0; k < 8; k++) {
                int idx = t + 128*k;
                *(float4*)(ws + idx*4) = *(const float4*)(W7p + idx*4);
            }
        }
        __syncthreads();

        // acc[r][m]: m=0,1 -> cols 4cg..4cg+3 ; m=2,3 -> cols 32+4cg..+3
        ull acc[4][4];
        #pragma unroll
        for (int r = 0; r < 4; r++)
            #pragma unroll
            for (int m = 0; m < 4; m++) acc[r][m] = 0ULL;

        #pragma unroll 8
        for (int d = 0; d < 64; d++) {
            ulonglong2 w0 = *(const ulonglong2*)&ws[d*64 + cg*4];
            ulonglong2 w1 = *(const ulonglong2*)&ws[d*64 + 32 + cg*4];
            ull xr[4];
            #pragma unroll
            for (int r = 0; r < 4; r++) xr[r] = pack2(xs[d*64 + r0 + r]);
            #pragma unroll
            for (int r = 0; r < 4; r++) {
                fma2(acc[r][0], xr[r], w0.x);
                fma2(acc[r][1], xr[r], w0.y);
                fma2(acc[r][2], xr[r], w1.x);
                fma2(acc[r][3], xr[r], w1.y);
            }
        }

        #pragma unroll
        for (int r = 0; r < 4; r++) {
            float2 v0 = unpack2(acc[r][0]), v1 = unpack2(acc[r][1]);
            float2 v2 = unpack2(acc[r][2]), v3 = unpack2(acc[r][3]);
            int row = p0 + r0 + r;
            float* base = g_uhl + j*1048576 + row*64;
            *(float4*)(base + 4*cg)      = make_float4(v0.x, v0.y, v1.x, v1.y);
            *(float4*)(base + 32 + 4*cg) = make_float4(v2.x, v2.y, v3.x, v3.y);

            float s = v0.x*v0.x + v0.y*v0.y + v1.x*v1.x + v1.y*v1.y
                    + v2.x*v2.x + v2.y*v2.y + v3.x*v3.x + v3.y*v3.y;
            #pragma unroll
            for (int off = 1; off < 8; off <<= 1)
                s += __shfl_xor_sync(~0u, s, off);
            if (cg == 0) g_n2[j*16384 + row] = s;
        }
    }
}

// one routing reduction: c=softmax(B)[7,:]; t[j,d] += scal(b,j)*u[b,7,d]
// grid 256 blocks x 64 rows; 16 loads batched in regs before FMA chain.
__global__ __launch_bounds__(256) void k_route1(const float* __restrict__ x) {
    __shared__ float c_s[8];
    __shared__ float scal_s[64*8];
    __shared__ float red[4][512];
    int t = threadIdx.x;
    if (t < 8) {
        float m = g_B[t];
        #pragma unroll
        for (int i = 1; i < 8; i++) m = fmaxf(m, g_B[i*8+t]);
        float sum = 0.f, e7 = 0.f;
        #pragma unroll
        for (int i = 0; i < 8; i++) {
            float e = expf(g_B[i*8+t] - m);
            sum += e; if (i == 7) e7 = e;
        }
        c_s[t] = e7/sum;
    }
    __syncthreads();
    int p0 = blockIdx.x * 64;
    {   // scal table: 512 entries, 2 per thread
        int idx = t * 2;
        int r = idx >> 3, j = idx & 7;
        scal_s[idx]   = squash_scal(c_s[j],   g_n2[j*16384     + p0 + r]);
        scal_s[idx+1] = squash_scal(c_s[j+1], g_n2[(j+1)*16384 + p0 + r]);
    }
    __syncthreads();
    int d = t & 63, g = t >> 6;          // 4 groups x 16 rows
    const float* xb = x + X7 + d;
    float xv[16];
    #pragma unroll
    for (int m = 0; m < 16; m++)         // 16 independent loads in flight
        xv[m] = xb[xrow(p0 + g*16 + m)*64];
    float acc[8] = {0,0,0,0,0,0,0,0};
    #pragma unroll
    for (int m = 0; m < 16; m++) {
        int r = g*16 + m;
        #pragma unroll
        for (int j = 0; j < 8; j++) acc[j] += scal_s[r*8+j] * xv[m];
    }
    #pragma unroll
    for (int j = 0; j < 8; j++) red[g][j*64+d] = acc[j];
    __syncthreads();
    #pragma unroll
    for (int o = 0; o < 2; o++) {
        int idx = t + 256*o;
        atomicAdd(&g_t[idx], red[0][idx]+red[1][idx]+red[2][idx]+red[3][idx]);
    }
}

// vmean[j,e] = (1/16384)*sum_d W7[j,d,e]*t[j,d]; B += uhm.vmean; g_c=softmax(B)[7]
__global__ __launch_bounds__(512) void k_route2(const float* __restrict__ w) {
    __shared__ float ts[512], vm[512];
    int t = threadIdx.x;           // 512
    ts[t] = g_t[t];
    __syncthreads();
    g_t[t] = 0.f;
    const float* W7p = w + W7OFF;
    {
        int j = t >> 6, e = t & 63;
        const float* wp = W7p + j*4096 + e;
        const float* tp = ts + j*64;
        float s = 0.f;
        #pragma unroll 8
        for (int d = 0; d < 64; d++) s += wp[d*64] * tp[d];
        vm[t] = s * (1.f/16384.f);
    }
    __syncthreads();
    if (t < 64) {
        int j = t & 7;
        float s = 0.f;
        #pragma unroll 8
        for (int e = 0; e < 64; e++) s += g_uhm[t*64 + e] * vm[j*64 + e];
        g_B[t] += s;
    }
    __syncthreads();
    if (t < 8) {
        float m = g_B[t];
        #pragma unroll
        for (int i = 1; i < 8; i++) m = fmaxf(m, g_B[i*8+t]);
        float sum = 0.f, e7 = 0.f;
        #pragma unroll
        for (int i = 0; i < 8; i++) {
            float e = expf(g_B[i*8+t] - m);
            sum += e; if (i == 7) e7 = e;
        }
        g_c[t] = e7/sum;
    }
}

// out[j,b,e] = scal3(j,b) * uhl[j,b,e]  (pure stream; output position == b)
__global__ void k_out(float* __restrict__ out) {
    __shared__ float scal_s[128];
    int j = blockIdx.y, p0 = blockIdx.x * 128, t = threadIdx.x;
    if (t < 128) scal_s[t] = squash_scal(g_c[j], g_n2[j*16384 + p0 + t]);
    __syncthreads();
    const float4* src = (const float4*)(g_uhl + j*1048576 + p0*64);
    float4* dst = (float4*)(out + j*1048576 + p0*64);
    #pragma unroll
    for (int k = 0; k < 8; k++) {
        int idx = k*256 + t;       // 2048 float4
        float4 v = src[idx];
        float s = scal_s[idx >> 4];
        v.x *= s; v.y *= s; v.z *= s; v.w *= s;
        dst[idx] = v;
    }
}

extern "C" void kernel_launch(void* const* d_in, const int* in_sizes, int n_in,
                              void* d_out, int out_size) {
    const float* x = (const float*)d_in[0];
    const float* w = (const float*)d_in[1];
    float* out = (float*)d_out;
    k_gemm<<<dim3(256, 4), 128>>>(x, w);
    k_umean<<<dim3(16, 8), 256>>>(x);
    k_uhm<<<16, 256>>>(w);
    k_route1<<<256, 256>>>(x);
    k_route2<<<1, 512>>>(w);
    k_route1<<<256, 256>>>(x);
    k_route2<<<1, 512>>>(w);
    k_out<<<dim3(128, 8), 256>>>(out);
}